// round 12
// baseline (speedup 1.0000x reference)
#include <cuda_runtime.h>
#include <math.h>

// ---------------- problem constants ----------------
#define NS   4
#define BT   10
#define C    384
#define CTXC 128
#define DH   64
#define TI   128
#define MAXBLK 50
#define PSTRIDE 386
#define SCALE 0.125f

// flattened attn tiles: s0:500, s1:130, s2:40, s3:10 -> 680
#define TB0 500
#define TB1 630
#define TB2 670
#define NTILES 680

#define NF4 8160000
#define NGROUPS 340          // group of 5 = 2 attn + 3 fill; fill blk = 8000 float4
#define NPREP (NS*BT)

// ---------------- scratch ----------------
__device__ float g_wsim  [NS*BT*C];
__device__ float g_outvec[NS*BT*C];
__device__ float g_part  [NS*BT*MAXBLK*PSTRIDE];   // ~3.1 MB (L2-resident)
__device__ int   g_cnt   [NS*BT];   // monotonic; combine on (old % nblk)==nblk-1
__device__ int   g_done;            // monotonic gate (prep)

__constant__ int c_nblk[NS] = {50, 13, 4, 1};

// ================= ONE fused kernel: prep | attn | fill | combine =================
__global__ __launch_bounds__(512, 2) void k_all(
        const float* __restrict__ f0, const float* __restrict__ f1,
        const float* __restrict__ f2, const float* __restrict__ f3,
        const float* __restrict__ p0, const float* __restrict__ p1,
        const float* __restrict__ p2, const float* __restrict__ p3,
        const float* __restrict__ a0, const float* __restrict__ a1,
        const float* __restrict__ a2, const float* __restrict__ a3,
        const float* __restrict__ Wp, const float* __restrict__ bp,
        const float* __restrict__ pe,
        const float* __restrict__ Wqk, const float* __restrict__ Wcqk,
        const float* __restrict__ Wcv,
        const float* __restrict__ Wo,  const float* __restrict__ bo,
        const float* __restrict__ Wv,  const float* __restrict__ Wco,
        const float* __restrict__ bco,
        float4* __restrict__ out4)
{
    int tid = threadIdx.x;

    // =========================== PREP role ===========================
    if (blockIdx.x < NPREP) {
        int b = blockIdx.x % BT, s = blockIdx.x / BT;
        __shared__ float ash[CTXC];
        __shared__ float a_sh[C], apc_sh[C];
        __shared__ float psh[6][DH];
        __shared__ float cqk_sh[DH], cv_sh[DH];

        const float* au = (s==0 ? a0 : s==1 ? a1 : s==2 ? a2 : a3) + b*CTXC;
        if (tid < CTXC) ash[tid] = au[tid];
        __syncthreads();

        if (tid < C) {
            const float4* w = (const float4*)(Wp + ((size_t)s*C + tid)*CTXC);
            float acc0 = bp[s*C + tid], acc1 = 0.f;
            #pragma unroll
            for (int k = 0; k < 16; k++) {
                float4 wa = __ldg(&w[k]);
                float4 wb = __ldg(&w[k + 16]);
                acc0 += wa.x*ash[4*k]    + wa.y*ash[4*k+1]    + wa.z*ash[4*k+2]    + wa.w*ash[4*k+3];
                acc1 += wb.x*ash[64+4*k] + wb.y*ash[64+4*k+1] + wb.z*ash[64+4*k+2] + wb.w*ash[64+4*k+3];
            }
            float acc = acc0 + acc1;
            a_sh[tid]   = acc;
            apc_sh[tid] = acc + pe[((size_t)s*5 + (b%5))*C + tid];
        }
        __syncthreads();

        if (tid < C) {
            int o   = tid & 63;
            int grpI= tid >> 6;        // 0..5
            int mat = grpI & 1;
            int seg = grpI >> 1;
            const float* W = mat ? Wcv : Wcqk;
            const float* x = (mat ? a_sh : apc_sh) + seg*128;
            const float4* w = (const float4*)(W + ((size_t)s*DH + o)*C + seg*128);
            float acc0 = 0.f, acc1 = 0.f;
            #pragma unroll
            for (int k = 0; k < 16; k++) {
                float4 wa = __ldg(&w[k]);
                float4 wb = __ldg(&w[k + 16]);
                acc0 += wa.x*x[4*k]    + wa.y*x[4*k+1]    + wa.z*x[4*k+2]    + wa.w*x[4*k+3];
                acc1 += wb.x*x[64+4*k] + wb.y*x[64+4*k+1] + wb.z*x[64+4*k+2] + wb.w*x[64+4*k+3];
            }
            psh[grpI][o] = acc0 + acc1;
        }
        __syncthreads();
        if (tid < 128) {
            int mat = tid >> 6, o = tid & 63;
            float v = psh[mat][o] + psh[mat+2][o] + psh[mat+4][o];
            if (mat == 0) cqk_sh[o] = v; else cv_sh[o] = v;
        }
        __syncthreads();

        if (tid < C) {
            float ws0 = 0.f, ws1 = 0.f, ws2 = 0.f, ws3 = 0.f;
            const float* wq = Wqk + (size_t)s*DH*C + tid;
            #pragma unroll
            for (int d = 0; d < 16; d++) {
                ws0 += __ldg(wq + (size_t)(d     )*C) * cqk_sh[d];
                ws1 += __ldg(wq + (size_t)(d + 16)*C) * cqk_sh[d + 16];
                ws2 += __ldg(wq + (size_t)(d + 32)*C) * cqk_sh[d + 32];
                ws3 += __ldg(wq + (size_t)(d + 48)*C) * cqk_sh[d + 48];
            }
            float ov0 = bo[s*C + tid], ov1 = 0.f;
            const float4* w = (const float4*)(Wo + ((size_t)s*C + tid)*DH);
            #pragma unroll
            for (int k = 0; k < 8; k++) {
                float4 wa = __ldg(&w[k]);
                float4 wb = __ldg(&w[k + 8]);
                ov0 += wa.x*cv_sh[4*k]    + wa.y*cv_sh[4*k+1]    + wa.z*cv_sh[4*k+2]    + wa.w*cv_sh[4*k+3];
                ov1 += wb.x*cv_sh[32+4*k] + wb.y*cv_sh[32+4*k+1] + wb.z*cv_sh[32+4*k+2] + wb.w*cv_sh[32+4*k+3];
            }
            g_wsim  [((size_t)s*BT + b)*C + tid] = (ws0 + ws1 + ws2 + ws3) * SCALE;
            g_outvec[((size_t)s*BT + b)*C + tid] = ov0 + ov1;
        }
        __threadfence();
        __syncthreads();
        if (tid == 0) atomicAdd(&g_done, 1);
        return;
    }

    // =========================== gate ===========================
    if (tid == 0) {
        while (*(volatile int*)&g_done < NPREP) __nanosleep(128);
    }
    __syncthreads();

    int w5   = blockIdx.x - NPREP;
    int grp  = w5 / 5, lane5 = w5 % 5;

    if (lane5 >= 2) {
        // ---------- fill role: 8000 float4 ----------
        int fb = grp*3 + (lane5 - 2);
        #pragma unroll
        for (int k = 0; k < 16; k++) {
            int loc = tid + k*512;
            if (loc < 8000) {
                int idx = fb * 8000 + loc;
                int row;
                if (idx < 6144000)      row = idx / 1600;
                else if (idx < 7680000) row = 3840  + (idx - 6144000) / 400;
                else if (idx < 8064000) row = 7680  + (idx - 7680000) / 100;
                else                    row = 11520 + (idx - 8064000) / 25;
                float v = __ldg(&g_outvec[row]);
                out4[idx] = make_float4(v, v, v, v);
            }
        }
        return;
    }

    // ---------- attn role: 128-token tile, warp = channel-group ----------
    __shared__ float sred[16*132];     // [g][token], pad 132
    __shared__ float p_sh[TI];
    __shared__ float wredm[4], wredz[4];
    __shared__ int   s_last;
    __shared__ float msh[MAXBLK], zsh[MAXBLK], esh[MAXBLK];
    __shared__ float wxsh[C];
    __shared__ float psh2[3][DH];
    __shared__ float cdsh[DH];
    __shared__ float mg_sh, z_sh;

    int t = grp*2 + lane5;
    int stage, hw, b, blk;
    const float *fmap, *pos;
    if (t < TB0)      { stage=0; hw=6400; b=t/50;       blk=t%50;       fmap=f0; pos=p0; }
    else if (t < TB1) { stage=1; hw=1600; b=(t-TB0)/13; blk=(t-TB0)%13; fmap=f1; pos=p1; }
    else if (t < TB2) { stage=2; hw=400;  b=(t-TB1)/4;  blk=(t-TB1)%4;  fmap=f2; pos=p2; }
    else              { stage=3; hw=100;  b=t-TB2;      blk=0;          fmap=f3; pos=p3; }

    int g    = tid >> 5;        // 0..15 channel group == warp id
    int lane = tid & 31;        // token quad
    int iBase = blk * TI;
    int tok0  = iBase + lane*4;
    bool valid = tok0 < hw;     // hw % 4 == 0 -> whole quad valid or invalid

    const float* wbase = g_wsim + ((size_t)stage*BT + b)*C;
    const float* fbp = fmap + (size_t)b*C*hw + (size_t)g*hw + tok0;
    const float* pbp = pos  + (size_t)b*C*hw + (size_t)g*hw + tok0;
    size_t step = (size_t)hw << 4;   // 16 channels ahead

    // ---- pass 1: stream f+p, per-quad score partials (warp reads 512B/instr)
    float s0 = 0.f, s1 = 0.f, s2 = 0.f, s3 = 0.f;
    if (valid) {
        const float* fp = fbp;
        const float* qp = pbp;
        const float* wp = wbase + g;
        #pragma unroll
        for (int k = 0; k < 24; k++) {
            float4 f4 = *(const float4*)fp;
            float4 p4 = __ldcs((const float4*)qp);
            float w = __ldg(wp);
            s0 += (f4.x + p4.x) * w;
            s1 += (f4.y + p4.y) * w;
            s2 += (f4.z + p4.z) * w;
            s3 += (f4.w + p4.w) * w;
            fp += step; qp += step; wp += 16;
        }
    }
    *(float4*)(sred + g*132 + lane*4) = make_float4(s0, s1, s2, s3);
    __syncthreads();

    float* pp = g_part + (size_t)(((size_t)stage*BT + b)*MAXBLK + blk) * PSTRIDE;
    int nblkT = c_nblk[stage];

    // ---- softmax over 128 tokens (first 4 warps own tokens; all warps shfl)
    float s = -1e30f, e = 0.f;
    if (tid < TI) {
        s = 0.f;
        #pragma unroll
        for (int gg = 0; gg < 16; gg++) s += sred[gg*132 + tid];
        if (iBase + tid >= hw) s = -1e30f;
    }
    {
        float m = s;
        #pragma unroll
        for (int o = 16; o; o >>= 1) m = fmaxf(m, __shfl_xor_sync(0xffffffffu, m, o));
        if (lane == 0 && g < 4) wredm[g] = m;
    }
    __syncthreads();
    float mg = fmaxf(fmaxf(wredm[0], wredm[1]), fmaxf(wredm[2], wredm[3]));
    if (tid < TI) { e = expf(s - mg); p_sh[tid] = e; }
    {
        float z = e;
        #pragma unroll
        for (int o = 16; o; o >>= 1) z += __shfl_xor_sync(0xffffffffu, z, o);
        if (lane == 0 && g < 4) wredz[g] = z;
    }
    __syncthreads();
    if (tid == 0) { pp[0] = mg; pp[1] = wredz[0] + wredz[1] + wredz[2] + wredz[3]; }

    // ---- pass 2: re-read f (L2-hot), weighted channel sums via warp butterfly
    {
        float4 q = *(const float4*)(p_sh + lane*4);
        const float* fp = fbp;
        #pragma unroll
        for (int k = 0; k < 24; k++) {
            float wv = 0.f;
            if (valid) {
                float4 f4 = __ldcs((const float4*)fp);
                wv = f4.x*q.x + f4.y*q.y + f4.z*q.z + f4.w*q.w;
            }
            fp += step;
            #pragma unroll
            for (int o = 16; o; o >>= 1) wv += __shfl_xor_sync(0xffffffffu, wv, o);
            if (lane == 0) pp[2 + g + (k << 4)] = wv;
        }
    }

    // ---------- last block of this (stage,b) this launch: combine ----------
    __threadfence();
    if (tid == 0) {
        int old = atomicAdd(&g_cnt[stage*BT + b], 1);
        s_last = ((old % nblkT) == nblkT - 1);
    }
    __syncthreads();
    if (!s_last) return;

    const float* pb = g_part + (size_t)(((size_t)stage*BT + b)*MAXBLK) * PSTRIDE;

    if (tid < nblkT) {
        msh[tid] = pb[(size_t)tid*PSTRIDE];
        zsh[tid] = pb[(size_t)tid*PSTRIDE + 1];
    }
    __syncthreads();
    if (tid == 0) {
        float m = -1e30f;
        for (int k = 0; k < nblkT; k++) m = fmaxf(m, msh[k]);
        mg_sh = m;
    }
    __syncthreads();
    if (tid < nblkT) esh[tid] = expf(msh[tid] - mg_sh);
    __syncthreads();
    if (tid == 0) {
        float z = 0.f;
        for (int k = 0; k < nblkT; k++) z += zsh[k] * esh[k];
        z_sh = z;
    }
    __syncthreads();

    if (tid < C) {
        float inv = 1.f / z_sh;
        float x0=0.f,x1=0.f,x2=0.f,x3=0.f,x4=0.f,x5=0.f,x6=0.f,x7=0.f;
        const float* p2 = pb + 2 + tid;
        int k = 0;
        for (; k + 8 <= nblkT; k += 8) {
            x0 += esh[k  ] * __ldg(p2 + (size_t)(k  )*PSTRIDE);
            x1 += esh[k+1] * __ldg(p2 + (size_t)(k+1)*PSTRIDE);
            x2 += esh[k+2] * __ldg(p2 + (size_t)(k+2)*PSTRIDE);
            x3 += esh[k+3] * __ldg(p2 + (size_t)(k+3)*PSTRIDE);
            x4 += esh[k+4] * __ldg(p2 + (size_t)(k+4)*PSTRIDE);
            x5 += esh[k+5] * __ldg(p2 + (size_t)(k+5)*PSTRIDE);
            x6 += esh[k+6] * __ldg(p2 + (size_t)(k+6)*PSTRIDE);
            x7 += esh[k+7] * __ldg(p2 + (size_t)(k+7)*PSTRIDE);
        }
        for (; k < nblkT; k++) x0 += esh[k] * __ldg(p2 + (size_t)k*PSTRIDE);
        wxsh[tid] = ((x0+x1)+(x2+x3)+((x4+x5)+(x6+x7))) * inv;
    }
    __syncthreads();

    if (tid < 192) {
        int o = tid & 63, seg = tid >> 6;
        const float4* w = (const float4*)(Wv + ((size_t)stage*DH + o)*C + seg*128);
        const float* x = wxsh + seg*128;
        float acc = 0.f;
        #pragma unroll
        for (int k = 0; k < 32; k++) {
            float4 w4 = __ldg(&w[k]);
            acc += w4.x*x[4*k] + w4.y*x[4*k+1] + w4.z*x[4*k+2] + w4.w*x[4*k+3];
        }
        psh2[seg][o] = acc;
    }
    __syncthreads();
    if (tid < DH) cdsh[tid] = psh2[0][tid] + psh2[1][tid] + psh2[2][tid];
    __syncthreads();

    if (tid < C) {
        float o = bco[stage*C + tid];
        const float4* w = (const float4*)(Wco + ((size_t)stage*C + tid)*DH);
        #pragma unroll
        for (int k = 0; k < 16; k++) {
            float4 w4 = __ldg(&w[k]);
            o += w4.x*cdsh[4*k] + w4.y*cdsh[4*k+1] + w4.z*cdsh[4*k+2] + w4.w*cdsh[4*k+3];
        }
        float* outf = (float*)out4;
        outf[(size_t)32640000 + (size_t)stage*BT*C + (size_t)b*C + tid] = o;
    }
}

// ================= launch =================
extern "C" void kernel_launch(void* const* d_in, const int* in_sizes, int n_in,
                              void* d_out, int out_size)
{
    const float *fm[4], *ps[4], *au[4];
    bool interleaved = (in_sizes[1] == in_sizes[0]);
    for (int i = 0; i < 4; i++) {
        if (interleaved) {
            fm[i] = (const float*)d_in[3*i];
            ps[i] = (const float*)d_in[3*i + 1];
            au[i] = (const float*)d_in[3*i + 2];
        } else {
            fm[i] = (const float*)d_in[i];
            au[i] = (const float*)d_in[4 + i];
            ps[i] = (const float*)d_in[8 + i];
        }
    }
    const float* Wp  = (const float*)d_in[12];
    const float* bp  = (const float*)d_in[13];
    const float* pe  = (const float*)d_in[14];
    const float* Wqk = (const float*)d_in[15];
    const float* Wcqk= (const float*)d_in[16];
    const float* Wv  = (const float*)d_in[17];
    const float* Wcv = (const float*)d_in[18];
    const float* Wo  = (const float*)d_in[19];
    const float* bo  = (const float*)d_in[20];
    const float* Wco = (const float*)d_in[21];
    const float* bco = (const float*)d_in[22];
    float* out = (float*)d_out;

    k_all<<<NPREP + NGROUPS*5, 512>>>(fm[0], fm[1], fm[2], fm[3],
                                      ps[0], ps[1], ps[2], ps[3],
                                      au[0], au[1], au[2], au[3],
                                      Wp, bp, pe, Wqk, Wcqk, Wcv, Wo, bo,
                                      Wv, Wco, bco,
                                      (float4*)out);
}

// round 15
// speedup vs baseline: 1.1218x; 1.1218x over previous
#include <cuda_runtime.h>
#include <math.h>

// ---------------- problem constants ----------------
#define NS   4
#define BT   10
#define C    384
#define CTXC 128
#define DH   64
#define TI   32
#define MAXBLK 200
#define PSTRIDE 386
#define SCALE 0.125f

#define TB0 2000
#define TB1 2500
#define TB2 2630
#define NTILES 2670

#define NF4 8160000
#define NFILL 3985            // 2048 float4 per fill block
#define NPREP (NS*BT)

// ---------------- scratch ----------------
__device__ float g_wsim  [NS*BT*C];
__device__ float g_outvec[NS*BT*C];
__device__ float g_part  [NS*BT*MAXBLK*PSTRIDE];
__device__ int   g_cnt   [NS*BT];   // monotonic; combine on (old % nblk)==nblk-1
__device__ int   g_done;            // monotonic gate (prep)

__constant__ int c_nblk[NS] = {200, 50, 13, 4};

// ===== ONE fused kernel; block roles TIME-SEGREGATED: prep | attn(reads) | fill(writes) =====
__global__ __launch_bounds__(512, 2) void k_all(
        const float* __restrict__ f0, const float* __restrict__ f1,
        const float* __restrict__ f2, const float* __restrict__ f3,
        const float* __restrict__ p0, const float* __restrict__ p1,
        const float* __restrict__ p2, const float* __restrict__ p3,
        const float* __restrict__ a0, const float* __restrict__ a1,
        const float* __restrict__ a2, const float* __restrict__ a3,
        const float* __restrict__ Wp, const float* __restrict__ bp,
        const float* __restrict__ pe,
        const float* __restrict__ Wqk, const float* __restrict__ Wcqk,
        const float* __restrict__ Wcv,
        const float* __restrict__ Wo,  const float* __restrict__ bo,
        const float* __restrict__ Wv,  const float* __restrict__ Wco,
        const float* __restrict__ bco,
        float4* __restrict__ out4)
{
    int tid = threadIdx.x;

    // =========================== PREP role ===========================
    if (blockIdx.x < NPREP) {
        int b = blockIdx.x % BT, s = blockIdx.x / BT;
        __shared__ float ash[CTXC];
        __shared__ float a_sh[C], apc_sh[C];
        __shared__ float psh[6][DH];
        __shared__ float cqk_sh[DH], cv_sh[DH];

        const float* au = (s==0 ? a0 : s==1 ? a1 : s==2 ? a2 : a3) + b*CTXC;
        if (tid < CTXC) ash[tid] = au[tid];
        __syncthreads();

        if (tid < C) {
            const float4* w = (const float4*)(Wp + ((size_t)s*C + tid)*CTXC);
            float acc0 = bp[s*C + tid], acc1 = 0.f;
            #pragma unroll
            for (int k = 0; k < 16; k++) {
                float4 wa = __ldg(&w[k]);
                float4 wb = __ldg(&w[k + 16]);
                acc0 += wa.x*ash[4*k]    + wa.y*ash[4*k+1]    + wa.z*ash[4*k+2]    + wa.w*ash[4*k+3];
                acc1 += wb.x*ash[64+4*k] + wb.y*ash[64+4*k+1] + wb.z*ash[64+4*k+2] + wb.w*ash[64+4*k+3];
            }
            float acc = acc0 + acc1;
            a_sh[tid]   = acc;
            apc_sh[tid] = acc + pe[((size_t)s*5 + (b%5))*C + tid];
        }
        __syncthreads();

        if (tid < C) {
            int o   = tid & 63;
            int grpI= tid >> 6;        // 0..5
            int mat = grpI & 1;
            int seg = grpI >> 1;
            const float* W = mat ? Wcv : Wcqk;
            const float* x = (mat ? a_sh : apc_sh) + seg*128;
            const float4* w = (const float4*)(W + ((size_t)s*DH + o)*C + seg*128);
            float acc0 = 0.f, acc1 = 0.f;
            #pragma unroll
            for (int k = 0; k < 16; k++) {
                float4 wa = __ldg(&w[k]);
                float4 wb = __ldg(&w[k + 16]);
                acc0 += wa.x*x[4*k]    + wa.y*x[4*k+1]    + wa.z*x[4*k+2]    + wa.w*x[4*k+3];
                acc1 += wb.x*x[64+4*k] + wb.y*x[64+4*k+1] + wb.z*x[64+4*k+2] + wb.w*x[64+4*k+3];
            }
            psh[grpI][o] = acc0 + acc1;
        }
        __syncthreads();
        if (tid < 128) {
            int mat = tid >> 6, o = tid & 63;
            float v = psh[mat][o] + psh[mat+2][o] + psh[mat+4][o];
            if (mat == 0) cqk_sh[o] = v; else cv_sh[o] = v;
        }
        __syncthreads();

        if (tid < C) {
            float ws0 = 0.f, ws1 = 0.f, ws2 = 0.f, ws3 = 0.f;
            const float* wq = Wqk + (size_t)s*DH*C + tid;
            #pragma unroll
            for (int d = 0; d < 16; d++) {
                ws0 += __ldg(wq + (size_t)(d     )*C) * cqk_sh[d];
                ws1 += __ldg(wq + (size_t)(d + 16)*C) * cqk_sh[d + 16];
                ws2 += __ldg(wq + (size_t)(d + 32)*C) * cqk_sh[d + 32];
                ws3 += __ldg(wq + (size_t)(d + 48)*C) * cqk_sh[d + 48];
            }
            float ov0 = bo[s*C + tid], ov1 = 0.f;
            const float4* w = (const float4*)(Wo + ((size_t)s*C + tid)*DH);
            #pragma unroll
            for (int k = 0; k < 8; k++) {
                float4 wa = __ldg(&w[k]);
                float4 wb = __ldg(&w[k + 8]);
                ov0 += wa.x*cv_sh[4*k]    + wa.y*cv_sh[4*k+1]    + wa.z*cv_sh[4*k+2]    + wa.w*cv_sh[4*k+3];
                ov1 += wb.x*cv_sh[32+4*k] + wb.y*cv_sh[32+4*k+1] + wb.z*cv_sh[32+4*k+2] + wb.w*cv_sh[32+4*k+3];
            }
            g_wsim  [((size_t)s*BT + b)*C + tid] = (ws0 + ws1 + ws2 + ws3) * SCALE;
            g_outvec[((size_t)s*BT + b)*C + tid] = ov0 + ov1;
        }
        __threadfence();
        __syncthreads();
        if (tid == 0) atomicAdd(&g_done, 1);
        return;
    }

    // =========================== gate ===========================
    if (tid == 0) {
        while (*(volatile int*)&g_done < NPREP) __nanosleep(128);
    }
    __syncthreads();

    // =========================== FILL role (all writes; scheduled LAST) ===========================
    if (blockIdx.x >= NPREP + NTILES) {
        int fb = blockIdx.x - (NPREP + NTILES);
        int base = fb * 2048 + tid;
        #pragma unroll
        for (int k = 0; k < 4; k++) {
            int idx = base + k*512;
            if (idx < NF4) {
                int row;
                if (idx < 6144000)      row = idx / 1600;
                else if (idx < 7680000) row = 3840  + (idx - 6144000) / 400;
                else if (idx < 8064000) row = 7680  + (idx - 7680000) / 100;
                else                    row = 11520 + (idx - 8064000) / 25;
                float v = __ldg(&g_outvec[row]);
                out4[idx] = make_float4(v, v, v, v);
            }
        }
        return;
    }

    // =========================== ATTN role (all reads; scheduled FIRST after prep) ===========================
    __shared__ float sred2[16*36];
    __shared__ float p_sh[TI];
    __shared__ int   s_last;
    __shared__ float msh[MAXBLK], zsh[MAXBLK], esh[MAXBLK];
    __shared__ float wxsh[C];
    __shared__ float psh2[3][DH];
    __shared__ float cdsh[DH];
    __shared__ float mg_sh, z_sh;

    int t = blockIdx.x - NPREP;
    int stage, hw, b, blk;
    const float *fmap, *pos;
    if (t < TB0)      { stage=0; hw=6400; b=t/200;      blk=t%200;      fmap=f0; pos=p0; }
    else if (t < TB1) { stage=1; hw=1600; b=(t-TB0)/50; blk=(t-TB0)%50; fmap=f1; pos=p1; }
    else if (t < TB2) { stage=2; hw=400;  b=(t-TB1)/13; blk=(t-TB1)%13; fmap=f2; pos=p2; }
    else              { stage=3; hw=100;  b=(t-TB2)/4;  blk=(t-TB2)%4;  fmap=f3; pos=p3; }

    int g    = tid >> 3;        // 0..63
    int j4   = tid & 7;
    int lane = tid & 31;
    int warp = tid >> 5;
    int iBase = blk * TI;
    int tok0  = iBase + j4*4;
    bool valid = tok0 < hw;

    const float* wbase = g_wsim + ((size_t)stage*BT + b)*C;

    float4 fc[6];
    float a0_ = 0.f, a1_ = 0.f, a2_ = 0.f, a3_ = 0.f;
    if (valid) {
        const float* fbp = fmap + (size_t)b*C*hw + tok0;
        const float* pbp = pos  + (size_t)b*C*hw + tok0;
        #pragma unroll
        for (int k = 0; k < 6; k++) {
            int c = g + (k << 6);
            size_t off = (size_t)c * hw;
            float4 f4 = *(const float4*)(fbp + off);
            float4 p4 = *(const float4*)(pbp + off);
            float w = __ldg(wbase + c);
            fc[k] = f4;
            a0_ += (f4.x + p4.x) * w;
            a1_ += (f4.y + p4.y) * w;
            a2_ += (f4.z + p4.z) * w;
            a3_ += (f4.w + p4.w) * w;
        }
    } else {
        #pragma unroll
        for (int k = 0; k < 6; k++) fc[k] = make_float4(0.f,0.f,0.f,0.f);
    }

    #pragma unroll
    for (int o = 8; o <= 16; o <<= 1) {
        a0_ += __shfl_xor_sync(0xffffffffu, a0_, o);
        a1_ += __shfl_xor_sync(0xffffffffu, a1_, o);
        a2_ += __shfl_xor_sync(0xffffffffu, a2_, o);
        a3_ += __shfl_xor_sync(0xffffffffu, a3_, o);
    }
    if (lane < 8)
        *(float4*)(sred2 + warp*36 + j4*4) = make_float4(a0_, a1_, a2_, a3_);
    __syncthreads();

    float* pp = g_part + (size_t)(((size_t)stage*BT + b)*MAXBLK + blk) * PSTRIDE;
    int nblkT = c_nblk[stage];

    if (tid < 32) {
        float s = 0.f;
        #pragma unroll
        for (int w = 0; w < 16; w++) s += sred2[w*36 + tid];
        if (iBase + tid >= hw) s = -1e30f;
        float m = s;
        #pragma unroll
        for (int o = 16; o; o >>= 1) m = fmaxf(m, __shfl_xor_sync(0xffffffffu, m, o));
        float e = expf(s - m);
        p_sh[tid] = e;
        float z = e;
        #pragma unroll
        for (int o = 16; o; o >>= 1) z += __shfl_xor_sync(0xffffffffu, z, o);
        if (tid == 0) { pp[0] = m; pp[1] = z; }
    }
    __syncthreads();

    {
        float q0 = p_sh[j4*4 + 0], q1 = p_sh[j4*4 + 1];
        float q2 = p_sh[j4*4 + 2], q3 = p_sh[j4*4 + 3];
        #pragma unroll
        for (int k = 0; k < 6; k++) {
            float w = fc[k].x*q0 + fc[k].y*q1 + fc[k].z*q2 + fc[k].w*q3;
            w += __shfl_xor_sync(0xffffffffu, w, 1, 8);
            w += __shfl_xor_sync(0xffffffffu, w, 2, 8);
            w += __shfl_xor_sync(0xffffffffu, w, 4, 8);
            if (j4 == 0) pp[2 + g + (k << 6)] = w;
        }
    }

    // ---------- last attn block of this (stage,b) this launch: combine ----------
    __threadfence();
    if (tid == 0) {
        int old = atomicAdd(&g_cnt[stage*BT + b], 1);
        s_last = ((old % nblkT) == nblkT - 1);
    }
    __syncthreads();
    if (!s_last) return;

    const float* pb = g_part + (size_t)(((size_t)stage*BT + b)*MAXBLK) * PSTRIDE;

    if (tid < nblkT) {
        msh[tid] = pb[(size_t)tid*PSTRIDE];
        zsh[tid] = pb[(size_t)tid*PSTRIDE + 1];
    }
    __syncthreads();
    if (tid == 0) {
        float m = -1e30f;
        for (int k = 0; k < nblkT; k++) m = fmaxf(m, msh[k]);
        mg_sh = m;
    }
    __syncthreads();
    if (tid < nblkT) esh[tid] = expf(msh[tid] - mg_sh);
    __syncthreads();
    if (tid == 0) {
        float z = 0.f;
        for (int k = 0; k < nblkT; k++) z += zsh[k] * esh[k];
        z_sh = z;
    }
    __syncthreads();

    if (tid < C) {
        float inv = 1.f / z_sh;
        float x0=0.f,x1=0.f,x2=0.f,x3=0.f,x4=0.f,x5=0.f,x6=0.f,x7=0.f;
        const float* p2 = pb + 2 + tid;
        int k = 0;
        for (; k + 8 <= nblkT; k += 8) {
            x0 += esh[k  ] * __ldg(p2 + (size_t)(k  )*PSTRIDE);
            x1 += esh[k+1] * __ldg(p2 + (size_t)(k+1)*PSTRIDE);
            x2 += esh[k+2] * __ldg(p2 + (size_t)(k+2)*PSTRIDE);
            x3 += esh[k+3] * __ldg(p2 + (size_t)(k+3)*PSTRIDE);
            x4 += esh[k+4] * __ldg(p2 + (size_t)(k+4)*PSTRIDE);
            x5 += esh[k+5] * __ldg(p2 + (size_t)(k+5)*PSTRIDE);
            x6 += esh[k+6] * __ldg(p2 + (size_t)(k+6)*PSTRIDE);
            x7 += esh[k+7] * __ldg(p2 + (size_t)(k+7)*PSTRIDE);
        }
        for (; k < nblkT; k++) x0 += esh[k] * __ldg(p2 + (size_t)k*PSTRIDE);
        wxsh[tid] = ((x0+x1)+(x2+x3)+((x4+x5)+(x6+x7))) * inv;
    }
    __syncthreads();

    if (tid < 192) {
        int o = tid & 63, seg = tid >> 6;
        const float4* w = (const float4*)(Wv + ((size_t)stage*DH + o)*C + seg*128);
        const float* x = wxsh + seg*128;
        float acc = 0.f;
        #pragma unroll
        for (int k = 0; k < 32; k++) {
            float4 w4 = __ldg(&w[k]);
            acc += w4.x*x[4*k] + w4.y*x[4*k+1] + w4.z*x[4*k+2] + w4.w*x[4*k+3];
        }
        psh2[seg][o] = acc;
    }
    __syncthreads();
    if (tid < DH) cdsh[tid] = psh2[0][tid] + psh2[1][tid] + psh2[2][tid];
    __syncthreads();

    if (tid < C) {
        float o = bco[stage*C + tid];
        const float4* w = (const float4*)(Wco + ((size_t)stage*C + tid)*DH);
        #pragma unroll
        for (int k = 0; k < 16; k++) {
            float4 w4 = __ldg(&w[k]);
            o += w4.x*cdsh[4*k] + w4.y*cdsh[4*k+1] + w4.z*cdsh[4*k+2] + w4.w*cdsh[4*k+3];
        }
        float* outf = (float*)out4;
        outf[(size_t)32640000 + (size_t)stage*BT*C + (size_t)b*C + tid] = o;
    }
}

// ================= launch =================
extern "C" void kernel_launch(void* const* d_in, const int* in_sizes, int n_in,
                              void* d_out, int out_size)
{
    const float *fm[4], *ps[4], *au[4];
    bool interleaved = (in_sizes[1] == in_sizes[0]);
    for (int i = 0; i < 4; i++) {
        if (interleaved) {
            fm[i] = (const float*)d_in[3*i];
            ps[i] = (const float*)d_in[3*i + 1];
            au[i] = (const float*)d_in[3*i + 2];
        } else {
            fm[i] = (const float*)d_in[i];
            au[i] = (const float*)d_in[4 + i];
            ps[i] = (const float*)d_in[8 + i];
        }
    }
    const float* Wp  = (const float*)d_in[12];
    const float* bp  = (const float*)d_in[13];
    const float* pe  = (const float*)d_in[14];
    const float* Wqk = (const float*)d_in[15];
    const float* Wcqk= (const float*)d_in[16];
    const float* Wv  = (const float*)d_in[17];
    const float* Wcv = (const float*)d_in[18];
    const float* Wo  = (const float*)d_in[19];
    const float* bo  = (const float*)d_in[20];
    const float* Wco = (const float*)d_in[21];
    const float* bco = (const float*)d_in[22];
    float* out = (float*)d_out;

    k_all<<<NPREP + NTILES + NFILL, 512>>>(fm[0], fm[1], fm[2], fm[3],
                                           ps[0], ps[1], ps[2], ps[3],
                                           au[0], au[1], au[2], au[3],
                                           Wp, bp, pe, Wqk, Wcqk, Wcv, Wo, bo,
                                           Wv, Wco, bco,
                                           (float4*)out);
}